// round 1
// baseline (speedup 1.0000x reference)
#include <cuda_runtime.h>
#include <cuda_bf16.h>

#define D         512
#define NTAU      100
#define HSLOTS    128          // power-of-2 circular history, >> NTAU+2
#define CTAS      128
#define ROWS_PER_CTA 4
#define THREADS   128

// Persistent device state (no allocations allowed).
__device__ float g_hist[HSLOTS * D];   // circular state history, slot-contiguous
__device__ int   g_count;              // monotonic barrier counter

__global__ void reset_kernel() { g_count = 0; }

__global__ void __launch_bounds__(THREADS, 1) ndde_kernel(
    const float* __restrict__ x0,
    const float* __restrict__ tau,
    const float* __restrict__ W1,
    const float* __restrict__ W2,
    const float* __restrict__ b,
    float* __restrict__ out,
    int N)
{
    __shared__ float w1s[ROWS_PER_CTA][D];
    __shared__ float w2s[ROWS_PER_CTA][D];

    const int tid  = threadIdx.x;
    const int warp = tid >> 5;
    const int lane = tid & 31;
    const int row  = blockIdx.x * ROWS_PER_CTA + warp;  // this warp's output row
    const long NP1 = (long)N + 1;

    // ---- one-time: stage this CTA's 4 rows of W1/W2 into shared memory ----
    #pragma unroll
    for (int w = 0; w < ROWS_PER_CTA; ++w) {
        const int r = blockIdx.x * ROWS_PER_CTA + w;
        for (int k = tid; k < D; k += THREADS) {
            w1s[w][k] = W1[r * D + k];
            w2s[w][k] = W2[r * D + k];
        }
    }

    const float dt  = 0.01f * __ldg(tau);
    const float b_r = __ldg(b + row);
    float x_r = __ldg(x0 + row);       // this warp's own state component

    // ---- init: publish x_0 (hist slot 0 + output column 0) ----
    if (lane == 0) {
        g_hist[0 * D + row] = x_r;
        out[(long)row * NP1 + 0] = x_r;
    }
    __syncthreads();
    if (tid == 0) {
        __threadfence();               // release our init writes
        atomicAdd(&g_count, 1);
    }

    for (int j = 0; j < N; ++j) {
        // ---- barrier j: wait until every CTA has published x_j ----
        if (tid == 0) {
            const int target = CTAS * (j + 1);
            while (*(volatile int*)&g_count < target) { }
            __threadfence();           // acquire
        }
        __syncthreads();

        const int xslot = j & (HSLOTS - 1);
        const int yslot = (j >= NTAU) ? ((j - NTAU) & (HSLOTS - 1)) : 0;
        const float* xs = &g_hist[xslot * D];
        const float* ys = &g_hist[yslot * D];

        // ---- z_r = W1[row]·x + W2[row]·y  (lane handles k = lane + 32i) ----
        float acc = 0.0f;
        #pragma unroll
        for (int i = 0; i < D / 32; ++i) {
            const int k = lane + 32 * i;
            const float xv = __ldcg(xs + k);   // L2-coherent (skip stale L1)
            const float yv = __ldcg(ys + k);
            acc = fmaf(w1s[warp][k], xv, acc);
            acc = fmaf(w2s[warp][k], yv, acc);
        }
        #pragma unroll
        for (int off = 16; off; off >>= 1)
            acc += __shfl_xor_sync(0xffffffffu, acc, off);

        if (lane == 0) {
            const float z = acc + b_r;
            x_r = fmaf(dt, tanhf(z), x_r);
            const int ws = (j + 1) & (HSLOTS - 1);
            g_hist[ws * D + row] = x_r;                  // publish for peers
            out[(long)row * NP1 + (j + 1)] = x_r;        // trajectory column
        }
        __syncthreads();
        if (tid == 0) {
            __threadfence();           // release x_{j+1}
            atomicAdd(&g_count, 1);    // signal barrier j+1
        }
    }
}

extern "C" void kernel_launch(void* const* d_in, const int* in_sizes, int n_in,
                              void* d_out, int out_size) {
    const float* x0  = (const float*)d_in[0];
    const float* tau = (const float*)d_in[1];
    const float* W1  = (const float*)d_in[2];
    const float* W2  = (const float*)d_in[3];
    const float* b   = (const float*)d_in[4];
    float* out = (float*)d_out;

    const int N = out_size / D - 1;    // out is [D, N+1]

    reset_kernel<<<1, 1>>>();
    ndde_kernel<<<CTAS, THREADS>>>(x0, tau, W1, W2, b, out, N);
}